// round 4
// baseline (speedup 1.0000x reference)
#include <cuda_runtime.h>

// NCC: image (8,3,1024,1024) f32, template (3,31,31) f32, stride 1, pad 15.
// out (8,1024,1024) f32 = mean_c[ conv(img, norm_t) / (sqrt(m2-m1^2)+eps) ], NaN->0
//
// R4 structure:
//   ncc_prep  : normalize template -> g_tA (aligned) + g_tB (shift-1) copies
//   ncc_denom : fused tile-local separable 31x31 box sums (smem only) ->
//               g_R = 1/(sqrt(var)+eps)   (var<0 -> NaN propagates, matches ref)
//   ncc_main  : pure template correlation (fma.rn.f32x2) + multiply by g_R
//               128 thr/block, 64x32 tile, 8x2 px/thread

#define EPSF 1e-9f
#define INV961 (1.0f/961.0f)
#define PLANE_ELEMS (24*1024*1024)

__device__ float g_tA[3][31][32];
__device__ float g_tB[3][31][32];
__device__ float g_R [PLANE_ELEMS];

__device__ __forceinline__ void dfma(float2 &d, const float2 a, const float2 b) {
    asm("fma.rn.f32x2 %0, %1, %2, %0;"
        : "+l"(reinterpret_cast<unsigned long long &>(d))
        : "l"(reinterpret_cast<const unsigned long long &>(a)),
          "l"(reinterpret_cast<const unsigned long long &>(b)));
}

// ---------------------------------------------------------------- template prep
__global__ void ncc_prep(const float* __restrict__ t) {
    const int c = blockIdx.x;
    const int lane = threadIdx.x;
    const float* tc = t + c * 961;
    float s = 0.f;
    for (int i = lane; i < 961; i += 32) s += tc[i];
#pragma unroll
    for (int o = 16; o > 0; o >>= 1) s += __shfl_xor_sync(0xffffffffu, s, o);
    const float mu = s * INV961;
    float v = 0.f;
    for (int i = lane; i < 961; i += 32) { float d = tc[i] - mu; v = fmaf(d, d, v); }
#pragma unroll
    for (int o = 16; o > 0; o >>= 1) v += __shfl_xor_sync(0xffffffffu, v, o);
    const float sd = sqrtf(v * INV961);
    const float scale = 1.f / ((sd + EPSF) * 961.f);
    for (int idx = lane; idx < 31 * 32; idx += 32) {
        const int ri = idx >> 5, j = idx & 31;
        g_tA[c][ri][j] = (j < 31) ? (tc[ri * 31 + j] - mu) * scale : 0.f;
        g_tB[c][ri][j] = (j < 30) ? (tc[ri * 31 + j + 1] - mu) * scale : 0.f;
    }
}

// ---------------------------------------------------------------- fused denominator
// one block per 32x32 output tile per plane; 256 threads.
__global__ __launch_bounds__(256)
void ncc_denom(const float* __restrict__ img) {
    __shared__ float halo[62][65];   // stride 65 -> conflict-free row walks
    __shared__ float h1[62][32];
    __shared__ float h2[62][32];
    const int tid = threadIdx.x;
    const int gx0 = blockIdx.x << 5, gy0 = blockIdx.y << 5, pl = blockIdx.z;
    const float* plane = img + ((size_t)pl << 20);

    // load 62x62 halo (zero outside image)
    {
        const int col = tid & 63;
        const int gx = gx0 - 15 + col;
        const bool xok = (col < 62) && ((unsigned)gx < 1024u);
#pragma unroll 1
        for (int r = tid >> 6; r < 62; r += 4) {
            const int gy = gy0 - 15 + r;
            float v = 0.f;
            if (xok && ((unsigned)gy < 1024u)) v = plane[((size_t)gy << 10) + gx];
            halo[r][col] = v;
        }
    }
    __syncthreads();

    // horizontal sliding 31-box per row (62 rows x {sum, sumsq})
    if (tid < 124) {
        const int r = tid >> 1;
        if ((tid & 1) == 0) {
            float s = 0.f;
#pragma unroll
            for (int j = 0; j < 31; ++j) s += halo[r][j];
            h1[r][0] = s;
#pragma unroll 1
            for (int x = 1; x < 32; ++x) { s += halo[r][x + 30] - halo[r][x - 1]; h1[r][x] = s; }
        } else {
            float s = 0.f;
#pragma unroll
            for (int j = 0; j < 31; ++j) { const float f = halo[r][j]; s = fmaf(f, f, s); }
            h2[r][0] = s;
#pragma unroll 1
            for (int x = 1; x < 32; ++x) {
                const float fn = halo[r][x + 30], fo = halo[r][x - 1];
                s += fn * fn - fo * fo;
                h2[r][x] = s;
            }
        }
    }
    __syncthreads();

    // vertical sliding 31-box + finalize; warp 0, thread = column (coalesced stores)
    if (tid < 32) {
        float S1 = 0.f, S2 = 0.f;
#pragma unroll 1
        for (int r = 0; r < 31; ++r) { S1 += h1[r][tid]; S2 += h2[r][tid]; }
        float* Rp = g_R + ((size_t)pl << 20) + ((size_t)gy0 << 10) + gx0 + tid;
#pragma unroll 1
        for (int y = 0; y < 32; ++y) {
            const float m1 = S1 * INV961;
            const float var = fmaf(-m1, m1, S2 * INV961);
            Rp[(size_t)y << 10] = 1.f / (sqrtf(var) + EPSF);   // var<0 -> NaN propagates
            if (y < 31) {
                S1 += h1[y + 31][tid] - h1[y][tid];
                S2 += h2[y + 31][tid] - h2[y][tid];
            }
        }
    }
}

// ---------------------------------------------------------------- main correlation
__global__ __launch_bounds__(128, 4)
void ncc_main(const float* __restrict__ img, float* __restrict__ out) {
    __shared__ __align__(16) float sh_halo[62][100];    // cols 0..95 valid, stride 100
    __shared__ __align__(16) float sh_tA[31 * 32];
    __shared__ __align__(16) float sh_tB[31 * 32];

    const int tx = threadIdx.x;           // 0..7
    const int ty = threadIdx.y;           // 0..15
    const int tid = ty * 8 + tx;
    const int bx = blockIdx.x, by = blockIdx.y, n = blockIdx.z;
    const int gx0 = bx << 6, gy0 = by << 5;
    const int x0 = tx << 3, y0 = ty << 1;  // 8 wide x 2 tall per thread

    float oacc[2][8];
#pragma unroll
    for (int p = 0; p < 2; ++p)
#pragma unroll
        for (int k = 0; k < 8; ++k) oacc[p][k] = 0.f;

    for (int c = 0; c < 3; ++c) {
        __syncthreads();
        // templates
        {
            const float* gA = &g_tA[c][0][0];
            const float* gB = &g_tB[c][0][0];
#pragma unroll
            for (int i = 0; i < 8; ++i) {
                const int idx = tid + (i << 7);
                if (idx < 992) { sh_tA[idx] = gA[idx]; sh_tB[idx] = gB[idx]; }
            }
        }
        // halo: 62 rows x 96 cols (zero outside image)
        if (tid < 96) {
            const float* plane = img + ((size_t)(n * 3 + c) << 20);
            const int gx = gx0 - 15 + tid;
            const bool xok = (unsigned)gx < 1024u;
#pragma unroll 1
            for (int r = 0; r < 62; ++r) {
                const int gy = gy0 - 15 + r;
                float v = 0.f;
                if (xok && ((unsigned)gy < 1024u)) v = plane[((size_t)gy << 10) + gx];
                sh_halo[r][tid] = v;
            }
        }
        __syncthreads();

        float2 acc[2][8];
#pragma unroll
        for (int p = 0; p < 2; ++p)
#pragma unroll
            for (int k = 0; k < 8; ++k) acc[p][k] = make_float2(0.f, 0.f);

        // r = 0..31: p=0 uses i=r (0..30, skip 31); p=1 uses i=r-1 (0..30)
#pragma unroll 1
        for (int r = 0; r < 32; ++r) {
            const float* hrow = &sh_halo[y0 + r][x0];
            float4 Wv[10];
#pragma unroll
            for (int q = 0; q < 10; ++q) Wv[q] = *(const float4*)(hrow + (q << 2));
#pragma unroll
            for (int p = 0; p < 2; ++p) {
                const int i = r - p;
                if ((unsigned)i > 30u) continue;
                const float4* TA = (const float4*)(sh_tA + (i << 5));
                const float4* TB = (const float4*)(sh_tB + (i << 5));
                const float t0 = sh_tA[i << 5];
                float2 a0 = acc[p][0], a1 = acc[p][1], a2 = acc[p][2], a3 = acc[p][3];
                float2 a4 = acc[p][4], a5 = acc[p][5], a6 = acc[p][6], a7 = acc[p][7];
#pragma unroll
                for (int q = 0; q < 8; ++q) {
                    const float4 ta = TA[q], tb = TB[q];
                    const float2 A0 = make_float2(ta.x, ta.y), A1 = make_float2(ta.z, ta.w);
                    const float2 B0 = make_float2(tb.x, tb.y), B1 = make_float2(tb.z, tb.w);
                    const float2 P0 = make_float2(Wv[q].x,   Wv[q].y);
                    const float2 P1 = make_float2(Wv[q].z,   Wv[q].w);
                    const float2 P2 = make_float2(Wv[q+1].x, Wv[q+1].y);
                    const float2 P3 = make_float2(Wv[q+1].z, Wv[q+1].w);
                    const float2 P4 = make_float2(Wv[q+2].x, Wv[q+2].y);
                    const float2 P5 = make_float2(Wv[q+2].z, Wv[q+2].w);
                    dfma(a0, P0, A0); dfma(a2, P1, A0); dfma(a4, P2, A0); dfma(a6, P3, A0);
                    dfma(a1, P1, B0); dfma(a3, P2, B0); dfma(a5, P3, B0); dfma(a7, P4, B0);
                    dfma(a0, P1, A1); dfma(a2, P2, A1); dfma(a4, P3, A1); dfma(a6, P4, A1);
                    dfma(a1, P2, B1); dfma(a3, P3, B1); dfma(a5, P4, B1); dfma(a7, P5, B1);
                }
                a1.x = fmaf(Wv[0].y, t0, a1.x);   // odd pixels' tap-0 scalar
                a3.x = fmaf(Wv[0].w, t0, a3.x);
                a5.x = fmaf(Wv[1].y, t0, a5.x);
                a7.x = fmaf(Wv[1].w, t0, a7.x);
                acc[p][0] = a0; acc[p][1] = a1; acc[p][2] = a2; acc[p][3] = a3;
                acc[p][4] = a4; acc[p][5] = a5; acc[p][6] = a6; acc[p][7] = a7;
            }
        }

        // combine with precomputed reciprocal denominator
        {
            const float* Rpl = g_R + ((size_t)(n * 3 + c) << 20);
#pragma unroll
            for (int p = 0; p < 2; ++p) {
                const int gy = gy0 + y0 + p;
                const float* rp = Rpl + ((size_t)gy << 10) + gx0 + x0;
                const float4 r0 = *(const float4*)rp;
                const float4 r1 = *(const float4*)(rp + 4);
                oacc[p][0] += (acc[p][0].x + acc[p][0].y) * r0.x;
                oacc[p][1] += (acc[p][1].x + acc[p][1].y) * r0.y;
                oacc[p][2] += (acc[p][2].x + acc[p][2].y) * r0.z;
                oacc[p][3] += (acc[p][3].x + acc[p][3].y) * r0.w;
                oacc[p][4] += (acc[p][4].x + acc[p][4].y) * r1.x;
                oacc[p][5] += (acc[p][5].x + acc[p][5].y) * r1.y;
                oacc[p][6] += (acc[p][6].x + acc[p][6].y) * r1.z;
                oacc[p][7] += (acc[p][7].x + acc[p][7].y) * r1.w;
            }
        }
    }

    // write out: mean over channels, NaN -> 0
#pragma unroll
    for (int p = 0; p < 2; ++p) {
        float v[8];
#pragma unroll
        for (int k = 0; k < 8; ++k) {
            const float r = oacc[p][k] * (1.0f / 3.0f);
            v[k] = (r == r) ? r : 0.f;
        }
        float* dst = out + (((size_t)n << 20) + ((size_t)(gy0 + y0 + p) << 10) + gx0 + x0);
        *(float4*)dst       = make_float4(v[0], v[1], v[2], v[3]);
        *(float4*)(dst + 4) = make_float4(v[4], v[5], v[6], v[7]);
    }
}

extern "C" void kernel_launch(void* const* d_in, const int* in_sizes, int n_in,
                              void* d_out, int out_size) {
    (void)in_sizes; (void)n_in; (void)out_size;
    const float* img  = (const float*)d_in[0];
    const float* tmpl = (const float*)d_in[1];
    float* out = (float*)d_out;

    ncc_prep<<<3, 32>>>(tmpl);
    ncc_denom<<<dim3(32, 32, 24), 256>>>(img);
    ncc_main<<<dim3(16, 32, 8), dim3(8, 16)>>>(img, out);
}